// round 12
// baseline (speedup 1.0000x reference)
#include <cuda_runtime.h>
#include <cstdint>

// UnalignmentLoss: min over 17x17 shifts (step 2) of mean L1 between shifted
// x crop and fixed y center crop. x,y: (4,3,256,256) fp32, crop 224x224.
//
// One warp per (plane, shift-row i, 14-row chunk) -> 816 blocks = exactly one
// wave at 6 blocks/SM. x,y rows staged GMEM->SMEM via cp.async double-buffers;
// swizzled conflict-free LDS.128. 40-float x window ring-streamed (1 granule
// per 2 shifts, 4-granule lookahead) to keep register liveness low (no spills
// at the 85-reg cap). Packed f32x2 fma + 64-bit-AND abs; 17 scalar accums.
// Last block (atomic counter) does the 289-way min and resets state.

#define NS    17
#define W_    256
#define TOLC  16
#define COUNT_F 602112.0f          // 4*3*224*224
#define ROWS_PER_WARP 14
#define NBLOCKS (4 * NS * 12)      // 816

__device__ float g_acc[NS * NS];   // zero at load; last block restores 0
__device__ unsigned g_count;       // zero at load; last block restores 0

// ---- packed f32x2 helpers (uint64_t = b64 carrier) ----
__device__ __forceinline__ uint64_t f2add(uint64_t a, uint64_t b) {
    uint64_t r; asm("add.rn.f32x2 %0, %1, %2;" : "=l"(r) : "l"(a), "l"(b)); return r;
}
__device__ __forceinline__ uint64_t f2fma(uint64_t a, uint64_t b, uint64_t c) {
    uint64_t r; asm("fma.rn.f32x2 %0, %1, %2, %3;" : "=l"(r) : "l"(a), "l"(b), "l"(c)); return r;
}
__device__ __forceinline__ uint64_t f2abs(uint64_t a) {
    return a & 0x7FFFFFFF7FFFFFFFULL;
}
__device__ __forceinline__ void unpack2(uint64_t v, float& lo, float& hi) {
    asm("mov.b64 {%0, %1}, %2;" : "=f"(lo), "=f"(hi) : "l"(v));
}
__device__ __forceinline__ void lds_2b64(unsigned addr, uint64_t& a, uint64_t& b) {
    asm volatile("ld.shared.v2.b64 {%0,%1}, [%2];" : "=l"(a), "=l"(b) : "r"(addr));
}
__device__ __forceinline__ void cp16(unsigned saddr, const float* g) {
    asm volatile("cp.async.ca.shared.global [%0], [%1], 16;"
                 :: "r"(saddr), "l"(g) : "memory");
}
__device__ __forceinline__ void cp_commit() {
    asm volatile("cp.async.commit_group;" ::: "memory");
}
template <int N>
__device__ __forceinline__ void cp_wait() {
    asm volatile("cp.async.wait_group %0;" :: "n"(N) : "memory");
}
// XOR swizzle on 16B granule index (row = 64 granules): conflict-free for the
// 2-granule staging copies and the strided window reads.
__device__ __forceinline__ int swz(int t) { return t ^ ((t >> 3) & 7); }

#define NEG1_X2 0xBF800000BF800000ULL   // packed (-1.0f, -1.0f)

__global__ __launch_bounds__(128, 6) void corr_kernel(const float* __restrict__ x,
                                                      const float* __restrict__ y,
                                                      float* __restrict__ out) {
    const int warp = threadIdx.x >> 5;
    const int lane = threadIdx.x & 31;
    const int bc   = blockIdx.z;       // plane
    const int i    = blockIdx.y;       // shift-row index (shift = 2*i)
    const int r0   = blockIdx.x * (4 * ROWS_PER_WARP) + warp * ROWS_PER_WARP;

    const float* xb = x + (size_t)bc * (W_ * W_);
    const float* yb = y + (size_t)bc * (W_ * W_);

    __shared__ __align__(16) float xs[4][2][W_];   // [warp][double-buffer][256]
    __shared__ __align__(16) float ys[4][2][W_];   // y crop rows (224 used)
    __shared__ unsigned s_last;

    const unsigned xbase = (unsigned)__cvta_generic_to_shared(&xs[warp][0][0]);
    const unsigned ybase = (unsigned)__cvta_generic_to_shared(&ys[warp][0][0]);

    const int Lc = lane < 28 ? lane : 27;          // idle lanes: broadcast reads
    unsigned roff[10];
#pragma unroll
    for (int m = 0; m < 10; m++) roff[m] = (unsigned)(swz(2 * Lc + m) * 16);
    const unsigned s0 = (unsigned)(swz(2 * lane)     * 16);
    const unsigned s1 = (unsigned)(swz(2 * lane + 1) * 16);

    float acc[NS];
#pragma unroll
    for (int j = 0; j < NS; j++) acc[j] = 0.0f;

    // Prologue: async-copy x and y row 0 into buffer 0.
    {
        const float* xr = xb + (size_t)(2 * i + r0) * W_ + 8 * lane;
        cp16(xbase + s0, xr);
        cp16(xbase + s1, xr + 4);
        const float* yr = yb + (size_t)(TOLC + r0) * W_ + TOLC + 8 * lane;
        cp16(ybase + s0, yr);       // lanes 28-31 stage don't-care (in-bounds)
        cp16(ybase + s1, yr + 4);
        cp_commit();
    }

#pragma unroll 1
    for (int rr = 0; rr < ROWS_PER_WARP; rr++) {
        const unsigned boff  = (rr & 1) ? (unsigned)(W_ * 4) : 0u;
        const unsigned nboff = boff ^ (unsigned)(W_ * 4);

        // Prefetch x,y row rr+1 (clamped dup on last iter; harmless, in-bounds).
        const int rn = (rr < ROWS_PER_WARP - 1) ? rr + 1 : rr;
        const float* xn = xb + (size_t)(2 * i + r0 + rn) * W_ + 8 * lane;
        cp16(xbase + nboff + s0, xn);
        cp16(xbase + nboff + s1, xn + 4);
        const float* yn = yb + (size_t)(TOLC + r0 + rn) * W_ + TOLC + 8 * lane;
        cp16(ybase + nboff + s0, yn);
        cp16(ybase + nboff + s1, yn + 4);
        cp_commit();

        cp_wait<1>();       // row rr landed (only row rr+1 still in flight)
        __syncwarp();

        // y pairs for this lane's 8 columns (same swizzled slots it staged).
        uint64_t y0, y1, y2, y3;
        lds_2b64(ybase + boff + s0, y0, y1);
        lds_2b64(ybase + boff + s1, y2, y3);

        // Window pairs [4L, 4L+20): ring-streamed, 4-granule lookahead.
        uint64_t wd[20];
#pragma unroll
        for (int g = 0; g < 4; g++)   // preload granules 0..3 (pairs 0..7)
            lds_2b64(xbase + boff + roff[g], wd[2 * g], wd[2 * g + 1]);

#pragma unroll
        for (int j = 0; j < NS; j++) {
            if ((j & 1) == 0 && (j / 2 + 4) < 10) {   // lookahead granule load
                const int g = j / 2 + 4;
                lds_2b64(xbase + boff + roff[g], wd[2 * g], wd[2 * g + 1]);
            }
            uint64_t a0 = f2abs(f2fma(y0, NEG1_X2, wd[j + 0]));  // |x - y|
            uint64_t a1 = f2abs(f2fma(y1, NEG1_X2, wd[j + 1]));
            uint64_t a2 = f2abs(f2fma(y2, NEG1_X2, wd[j + 2]));
            uint64_t a3 = f2abs(f2fma(y3, NEG1_X2, wd[j + 3]));
            uint64_t t  = f2add(f2add(a0, a1), f2add(a2, a3));
            float lo, hi; unpack2(t, lo, hi);
            acc[j] += lo + hi;          // scalar accumulator (reg diet)
        }
    }
    cp_wait<0>();   // drain the dup prefetch before exit paths

    // Reduce: lane j keeps shift-column j's warp sum; idle lanes contribute 0.
    float keep = 0.0f;
#pragma unroll
    for (int j = 0; j < NS; j++) {
        float v = (lane < 28) ? acc[j] : 0.0f;
#pragma unroll
        for (int off = 16; off; off >>= 1) v += __shfl_xor_sync(0xffffffffu, v, off);
        if (lane == j) keep = v;
    }
    if (lane < NS) atomicAdd(&g_acc[i * NS + lane], keep);

    // ---- last-block finalize (threadFenceReduction pattern) ----
    __threadfence();
    if (threadIdx.x == 0) {
        unsigned t = atomicAdd(&g_count, 1u);
        s_last = (t == NBLOCKS - 1) ? 1u : 0u;
    }
    __syncthreads();
    if (s_last && threadIdx.x < 32) {
        volatile float* ga = g_acc;
        float v = 3.4e38f;
        for (int idx = lane; idx < NS * NS; idx += 32) v = fminf(v, ga[idx]);
        for (int idx = lane; idx < NS * NS; idx += 32) g_acc[idx] = 0.0f;  // reset
#pragma unroll
        for (int off = 16; off; off >>= 1)
            v = fminf(v, __shfl_xor_sync(0xffffffffu, v, off));
        if (lane == 0) { out[0] = v * (1.0f / COUNT_F); g_count = 0u; }
    }
}

extern "C" void kernel_launch(void* const* d_in, const int* in_sizes, int n_in,
                              void* d_out, int out_size) {
    (void)in_sizes; (void)n_in; (void)out_size;
    const float* x = (const float*)d_in[0];
    const float* y = (const float*)d_in[1];
    float* out = (float*)d_out;

    dim3 grid(4, NS, 12);
    corr_kernel<<<grid, 128>>>(x, y, out);
}